// round 1
// baseline (speedup 1.0000x reference)
#include <cuda_runtime.h>
#include <math.h>

// ---------------- problem constants ----------------
#define BB   4
#define SS   2048
#define DD   768
#define HH   12
#define HD   64
#define FF   3072
#define NTOK (BB*SS)          // 8192
#define BH   (BB*HH)          // 48
#define QSZ  ((long)BH*SS*HD) // 6,291,456 per Q/K/V

// ---------------- scratch layout (floats) ----------------
// single big __device__ array, addressed by offsets (no allocations anywhere)
#define OFF_H      0L
#define OFF_WQKV   (OFF_H      + (long)NTOK*DD)        //  6,291,456
#define OFF_BQKV   (OFF_WQKV   + (long)DD*3*DD)        // +1,769,472
#define OFF_QKV    (OFF_BQKV   + 3L*DD)                // +2,304
#define OFF_SCORES (OFF_QKV    + 3L*QSZ)               // +18,874,368
#define OFF_O      (OFF_SCORES + (long)BH*SS*SS)       // +201,326,592
#define OFF_OC     (OFF_O      + QSZ)
#define OFF_A      (OFF_OC     + (long)NTOK*DD)
#define OFF_H2     (OFF_A      + (long)NTOK*DD)
#define OFF_F      (OFF_H2     + (long)NTOK*DD)
#define SCRATCH_TOTAL (OFF_F   + (long)NTOK*FF)        // 278,595,840 floats ~1.11 GB

__device__ __align__(16) float g_scratch[SCRATCH_TOTAL];

__device__ __forceinline__ float gelu_exact(float x) {
    return 0.5f * x * (1.0f + erff(x * 0.70710678118654752f));
}

// ---------------- weight/bias repack: Wq/Wk/Wv [H,D,HD] -> [D, 3*D] ----------------
__global__ void pack_qkv_w(const float* __restrict__ Wq, const float* __restrict__ Wk,
                           const float* __restrict__ Wv, const float* __restrict__ bq,
                           const float* __restrict__ bk, const float* __restrict__ bv) {
    long idx = (long)blockIdx.x * blockDim.x + threadIdx.x;
    const long total = (long)DD * 3 * DD;
    if (idx < total) {
        int d = (int)(idx / (3 * DD));
        int c = (int)(idx % (3 * DD));
        int which = c / DD;
        int r = c - which * DD;
        int h = r >> 6, e = r & 63;
        const float* W = (which == 0) ? Wq : (which == 1) ? Wk : Wv;
        g_scratch[OFF_WQKV + idx] = W[((long)h * DD + d) * HD + e];
    }
    if (idx < 3 * DD) {
        int which = (int)(idx / DD);
        int r = (int)(idx % DD);
        const float* bb = (which == 0) ? bq : (which == 1) ? bk : bv;
        g_scratch[OFF_BQKV + idx] = bb[r];
    }
}

// ---------------- LayerNorm: one block per row of 768 ----------------
__global__ void ln_kernel(const float* __restrict__ xEx, long offX,
                          const float* __restrict__ g, const float* __restrict__ b,
                          long offOut) {
    const float* x = (xEx ? xEx : (const float*)(g_scratch + offX)) + (long)blockIdx.x * DD;
    float* out = g_scratch + offOut + (long)blockIdx.x * DD;
    int tid = threadIdx.x;
    float s = 0.f, s2 = 0.f;
    for (int i = tid; i < DD; i += 256) { float v = x[i]; s += v; s2 += v * v; }
    #pragma unroll
    for (int off = 16; off; off >>= 1) {
        s  += __shfl_down_sync(0xffffffffu, s,  off);
        s2 += __shfl_down_sync(0xffffffffu, s2, off);
    }
    __shared__ float sh[2][8];
    int wid = tid >> 5, lane = tid & 31;
    if (lane == 0) { sh[0][wid] = s; sh[1][wid] = s2; }
    __syncthreads();
    if (tid == 0) {
        float ts = 0.f, ts2 = 0.f;
        #pragma unroll
        for (int i = 0; i < 8; i++) { ts += sh[0][i]; ts2 += sh[1][i]; }
        float mean = ts * (1.0f / DD);
        float var = ts2 * (1.0f / DD) - mean * mean;
        sh[0][0] = mean;
        sh[1][0] = rsqrtf(var + 1e-5f);
    }
    __syncthreads();
    float mean = sh[0][0], rstd = sh[1][0];
    for (int i = tid; i < DD; i += 256)
        out[i] = (x[i] - mean) * rstd * g[i] + b[i];
}

// ---------------- softmax over score rows (scale 1/8 folded in) ----------------
__global__ void softmax_kernel() {
    float* p = g_scratch + OFF_SCORES + (long)blockIdx.x * SS;
    int tid = threadIdx.x;
    float vr[8];
    float mx = -1e30f;
    #pragma unroll
    for (int k = 0; k < 8; k++) {
        float v = p[k * 256 + tid] * 0.125f;
        vr[k] = v;
        mx = fmaxf(mx, v);
    }
    #pragma unroll
    for (int off = 16; off; off >>= 1)
        mx = fmaxf(mx, __shfl_down_sync(0xffffffffu, mx, off));
    __shared__ float sh[8];
    int wid = tid >> 5, lane = tid & 31;
    if (lane == 0) sh[wid] = mx;
    __syncthreads();
    if (tid == 0) {
        float m = sh[0];
        #pragma unroll
        for (int i = 1; i < 8; i++) m = fmaxf(m, sh[i]);
        sh[0] = m;
    }
    __syncthreads();
    mx = sh[0];
    __syncthreads();
    float s = 0.f;
    #pragma unroll
    for (int k = 0; k < 8; k++) { vr[k] = expf(vr[k] - mx); s += vr[k]; }
    #pragma unroll
    for (int off = 16; off; off >>= 1)
        s += __shfl_down_sync(0xffffffffu, s, off);
    if (lane == 0) sh[wid] = s;
    __syncthreads();
    if (tid == 0) {
        float t = 0.f;
        #pragma unroll
        for (int i = 0; i < 8; i++) t += sh[i];
        sh[0] = 1.0f / t;
    }
    __syncthreads();
    float inv = sh[0];
    #pragma unroll
    for (int k = 0; k < 8; k++) p[k * 256 + tid] = vr[k] * inv;
}

// ---------------- repack attn output [B,H,S,HD] -> [B,S,D] ----------------
__global__ void repack_o() {
    long idx = (long)blockIdx.x * blockDim.x + threadIdx.x;
    if (idx < (long)NTOK * DD) {
        int m = (int)(idx / DD);
        int c = (int)(idx % DD);
        int b = m >> 11, s = m & 2047;
        int h = c >> 6, e = c & 63;
        g_scratch[OFF_OC + idx] = g_scratch[OFF_O + (((long)(b * HH + h) * SS + s) * HD + e)];
    }
}

// ---------------- generic tiled fp32 SGEMM ----------------
// modes: 0 = C[m,n] = acc(+bias)          1 = QKV scatter epilogue (+bias)
//        2 = gelu(acc+bias)
template<int BM, int BN, int BK, int TM, int TN>
__global__ __launch_bounds__((BM/TM)*(BN/TN))
void sgemm(const float* __restrict__ Aex, long offA,
           const float* __restrict__ Bex, long offB,
           const float* __restrict__ biasEx, long offBias,
           float* __restrict__ Cex, long offC,
           int M, int N, int K, int lda, int ldb, int ldc,
           long sA, long sB, long sC, int transB, int mode) {
    constexpr int THREADS = (BM/TM) * (BN/TN);
    const float* A = Aex ? Aex : (const float*)(g_scratch + offA);
    const float* B = Bex ? Bex : (const float*)(g_scratch + offB);
    const float* bias = biasEx ? biasEx : (offBias >= 0 ? (const float*)(g_scratch + offBias) : (const float*)nullptr);
    float* C = Cex ? Cex : (g_scratch + offC);
    int bz = blockIdx.z;
    A += (long)bz * sA; B += (long)bz * sB; C += (long)bz * sC;

    __shared__ float As[BK][BM];
    __shared__ float Bs[BK][BN];

    int tid = threadIdx.x;
    int tx = tid % (BN / TN);
    int ty = tid / (BN / TN);
    int m0 = blockIdx.y * BM, n0 = blockIdx.x * BN;

    float acc[TM][TN] = {};

    for (int k0 = 0; k0 < K; k0 += BK) {
        // load A tile (transposed into smem), float4 along K
        #pragma unroll
        for (int v = tid; v < BM * BK / 4; v += THREADS) {
            int row = v / (BK / 4);
            int kq = v % (BK / 4);
            float4 t;
            if (m0 + row < M)
                t = *(const float4*)(A + (long)(m0 + row) * lda + k0 + kq * 4);
            else
                t = make_float4(0.f, 0.f, 0.f, 0.f);
            As[kq * 4 + 0][row] = t.x;
            As[kq * 4 + 1][row] = t.y;
            As[kq * 4 + 2][row] = t.z;
            As[kq * 4 + 3][row] = t.w;
        }
        // load B tile
        if (!transB) {
            #pragma unroll
            for (int v = tid; v < BK * BN / 4; v += THREADS) {
                int r = v / (BN / 4);
                int nq = v % (BN / 4);
                float4 t = *(const float4*)(B + (long)(k0 + r) * ldb + n0 + nq * 4);
                *(float4*)&Bs[r][nq * 4] = t;
            }
        } else {
            #pragma unroll
            for (int v = tid; v < BK * BN / 4; v += THREADS) {
                int col = v / (BK / 4);
                int kq = v % (BK / 4);
                float4 t = *(const float4*)(B + (long)(n0 + col) * ldb + k0 + kq * 4);
                Bs[kq * 4 + 0][col] = t.x;
                Bs[kq * 4 + 1][col] = t.y;
                Bs[kq * 4 + 2][col] = t.z;
                Bs[kq * 4 + 3][col] = t.w;
            }
        }
        __syncthreads();

        #pragma unroll
        for (int k = 0; k < BK; k++) {
            float ar[TM], br[TN];
            #pragma unroll
            for (int i = 0; i < TM; i += 4) {
                float4 t = *(const float4*)&As[k][ty * TM + i];
                ar[i] = t.x; ar[i+1] = t.y; ar[i+2] = t.z; ar[i+3] = t.w;
            }
            #pragma unroll
            for (int j = 0; j < TN; j += 4) {
                float4 t = *(const float4*)&Bs[k][tx * TN + j];
                br[j] = t.x; br[j+1] = t.y; br[j+2] = t.z; br[j+3] = t.w;
            }
            #pragma unroll
            for (int i = 0; i < TM; i++)
                #pragma unroll
                for (int j = 0; j < TN; j++)
                    acc[i][j] = fmaf(ar[i], br[j], acc[i][j]);
        }
        __syncthreads();
    }

    // epilogue
    #pragma unroll
    for (int i = 0; i < TM; i++) {
        int m = m0 + ty * TM + i;
        if (m >= M) continue;
        #pragma unroll
        for (int j = 0; j < TN; j++) {
            int n = n0 + tx * TN + j;
            if (n >= N) continue;
            float v = acc[i][j];
            if (bias) v += bias[n];
            if (mode == 2) v = gelu_exact(v);
            if (mode == 1) {
                int which = n / DD;
                int r = n - which * DD;
                int h = r >> 6, e = r & 63;
                int b = m >> 11, s = m & 2047;
                C[(long)which * QSZ + (((long)(b * HH + h) * SS + s) * HD + e)] = v;
            } else {
                C[(long)m * ldc + n] = v;
            }
        }
    }
}

// ---------------- launch ----------------
extern "C" void kernel_launch(void* const* d_in, const int* in_sizes, int n_in,
                              void* d_out, int out_size) {
    const float* x   = (const float*)d_in[0];
    const float* Wq  = (const float*)d_in[1];
    const float* bq  = (const float*)d_in[2];
    const float* Wk  = (const float*)d_in[3];
    const float* bk  = (const float*)d_in[4];
    const float* Wv  = (const float*)d_in[5];
    const float* bv  = (const float*)d_in[6];
    const float* Wo  = (const float*)d_in[7];
    const float* bo  = (const float*)d_in[8];
    const float* W1  = (const float*)d_in[9];
    const float* b1  = (const float*)d_in[10];
    const float* W2  = (const float*)d_in[11];
    const float* b2  = (const float*)d_in[12];
    const float* g1  = (const float*)d_in[13];
    const float* be1 = (const float*)d_in[14];
    const float* g2  = (const float*)d_in[15];
    const float* be2 = (const float*)d_in[16];
    float* out = (float*)d_out;

    // 1) pack QKV weights/biases
    {
        long total = (long)DD * 3 * DD;
        pack_qkv_w<<<(unsigned)((total + 255) / 256), 256>>>(Wq, Wk, Wv, bq, bk, bv);
    }
    // 2) LN1: x -> h
    ln_kernel<<<NTOK, 256>>>(x, -1, g1, be1, OFF_H);
    // 3) fused QKV GEMM: [8192,768] x [768,2304] -> Q,K,V in [B,H,S,HD]
    sgemm<128,128,8,8,8><<<dim3(3*DD/128, NTOK/128, 1), 256>>>(
        nullptr, OFF_H, nullptr, OFF_WQKV, nullptr, OFF_BQKV, nullptr, OFF_QKV,
        NTOK, 3*DD, DD, DD, 3*DD, 0, 0, 0, 0, 0, 1);
    // 4) scores = Q K^T (batched over 48 heads), transB
    sgemm<128,128,8,8,8><<<dim3(SS/128, SS/128, BH), 256>>>(
        nullptr, OFF_QKV, nullptr, OFF_QKV + QSZ, nullptr, -1, nullptr, OFF_SCORES,
        SS, SS, HD, HD, HD, SS,
        (long)SS*HD, (long)SS*HD, (long)SS*SS, 1, 0);
    // 5) softmax (scale 1/8 folded in)
    softmax_kernel<<<BH * SS, 256>>>();
    // 6) O = softmax(scores) @ V (batched)
    sgemm<128,64,8,8,4><<<dim3(HD/64, SS/128, BH), 256>>>(
        nullptr, OFF_SCORES, nullptr, OFF_QKV + 2*QSZ, nullptr, -1, nullptr, OFF_O,
        SS, HD, SS, SS, HD, HD,
        (long)SS*SS, (long)SS*HD, (long)SS*HD, 0, 0);
    // 7) concat heads: [B,H,S,HD] -> [B,S,D]
    repack_o<<<(unsigned)(((long)NTOK*DD + 255) / 256), 256>>>();
    // 8) O-proj: Oc @ Wo + bo -> a
    sgemm<128,128,8,8,8><<<dim3(DD/128, NTOK/128, 1), 256>>>(
        nullptr, OFF_OC, Wo, 0, bo, -1, nullptr, OFF_A,
        NTOK, DD, DD, DD, DD, DD, 0, 0, 0, 0, 0);
    // 9) LN2: a -> h2
    ln_kernel<<<NTOK, 256>>>(nullptr, OFF_A, g2, be2, OFF_H2);
    // 10) MLP1 + exact GELU: h2 @ W1 + b1 -> f
    sgemm<128,128,8,8,8><<<dim3(FF/128, NTOK/128, 1), 256>>>(
        nullptr, OFF_H2, W1, 0, b1, -1, nullptr, OFF_F,
        NTOK, FF, DD, DD, FF, FF, 0, 0, 0, 0, 2);
    // 11) MLP2: f @ W2 + b2 -> out
    sgemm<128,128,8,8,8><<<dim3(DD/128, NTOK/128, 1), 256>>>(
        nullptr, OFF_F, W2, 0, b2, -1, out, 0,
        NTOK, DD, FF, FF, DD, DD, 0, 0, 0, 0, 0);
}

// round 3
// speedup vs baseline: 2.4183x; 2.4183x over previous
#include <cuda_runtime.h>
#include <cuda_bf16.h>
#include <math.h>
#include <stdint.h>

// ---------------- problem constants ----------------
#define BB   4
#define SS   2048
#define DD   768
#define HH   12
#define HDIM 64
#define FF   3072
#define NTOK 8192
#define BH   48

// ---------------- bf16 scratch (hi at off, lo at off + count) ----------------
#define N_H     6291456L
#define N_WQKV  1769472L
#define N_QKV1  6291456L
#define N_PROBS 201326592L
#define N_OC    6291456L
#define N_WO    589824L
#define N_H2    6291456L
#define N_W1    2359296L
#define N_F     25165824L
#define N_W2    2359296L

#define HO_H     0L
#define HO_WQKV  (HO_H + 2*N_H)
#define HO_Q     (HO_WQKV + 2*N_WQKV)
#define HO_K     (HO_Q + 2*N_QKV1)
#define HO_V     (HO_K + 2*N_QKV1)
#define HO_PROBS (HO_V + 2*N_QKV1)
#define HO_OC    (HO_PROBS + 2*N_PROBS)
#define HO_WO    (HO_OC + 2*N_OC)
#define HO_H2    (HO_WO + 2*N_WO)
#define HO_W1    (HO_H2 + 2*N_H2)
#define HO_F     (HO_W1 + 2*N_W1)
#define HO_W2    (HO_F + 2*N_F)
#define H_TOTAL  (HO_W2 + 2*N_W2)

#define FO_SCORES 0L
#define FO_A      201326592L
#define FO_BQKV   (FO_A + 6291456L)
#define F_TOTAL   (FO_BQKV + 2304L)

__device__ __align__(16) __nv_bfloat16 h_scratch[H_TOTAL];
__device__ __align__(16) float        f_scratch[F_TOTAL];

// ---------------- small helpers ----------------
__device__ __forceinline__ void store_split(__nv_bfloat16* hi, __nv_bfloat16* lo,
                                            long idx, float v) {
    __nv_bfloat16 h = __float2bfloat16(v);
    hi[idx] = h;
    lo[idx] = __float2bfloat16(v - __bfloat162float(h));
}

__device__ __forceinline__ float gelu_exact(float x) {
    return 0.5f * x * (1.0f + erff(x * 0.70710678118654752f));
}

__device__ __forceinline__ void cpasync16(uint32_t dst, const void* src) {
    asm volatile("cp.async.cg.shared.global [%0], [%1], 16;\n" :: "r"(dst), "l"(src));
}
__device__ __forceinline__ void cp_commit() {
    asm volatile("cp.async.commit_group;\n");
}
template<int N> __device__ __forceinline__ void cp_wait() {
    asm volatile("cp.async.wait_group %0;\n" :: "n"(N));
}
__device__ __forceinline__ void ldm_x4(uint32_t* r, uint32_t addr) {
    asm volatile("ldmatrix.sync.aligned.m8n8.x4.shared.b16 {%0,%1,%2,%3}, [%4];\n"
                 : "=r"(r[0]), "=r"(r[1]), "=r"(r[2]), "=r"(r[3]) : "r"(addr));
}
__device__ __forceinline__ void mma16816(float* d, const uint32_t* a, const uint32_t* b) {
    asm volatile("mma.sync.aligned.m16n8k16.row.col.f32.bf16.bf16.f32 "
                 "{%0,%1,%2,%3},{%4,%5,%6,%7},{%8,%9},{%0,%1,%2,%3};\n"
                 : "+f"(d[0]), "+f"(d[1]), "+f"(d[2]), "+f"(d[3])
                 : "r"(a[0]), "r"(a[1]), "r"(a[2]), "r"(a[3]), "r"(b[0]), "r"(b[1]));
}

// ---------------- packing / conversion kernels ----------------
__global__ void pack_wqkv(const float* __restrict__ Wq, const float* __restrict__ Wk,
                          const float* __restrict__ Wv) {
    long idx = (long)blockIdx.x * blockDim.x + threadIdx.x;
    if (idx >= 2304L * 768) return;
    int n = (int)(idx / 768), k = (int)(idx % 768);
    int which = n / 768 == 0 ? (n / DD) : 0; // n<2304
    which = n / DD;
    int r = n - which * DD;
    int h = r >> 6, e = r & 63;
    const float* W = (which == 0) ? Wq : (which == 1) ? Wk : Wv;
    float v = W[(long)h * (DD * HDIM) + (long)k * HDIM + e];
    store_split(h_scratch + HO_WQKV, h_scratch + HO_WQKV + N_WQKV, idx, v);
}

__global__ void pack_bqkv(const float* __restrict__ bq, const float* __restrict__ bk,
                          const float* __restrict__ bv) {
    int idx = blockIdx.x * blockDim.x + threadIdx.x;
    if (idx >= 3 * DD) return;
    int which = idx / DD, r = idx % DD;
    const float* b = (which == 0) ? bq : (which == 1) ? bk : bv;
    f_scratch[FO_BQKV + idx] = b[r];
}

// out[n*K + k] = W[k*N + n], hi/lo
__global__ void transpose_w(const float* __restrict__ W, int K, int N, long outOff) {
    long idx = (long)blockIdx.x * blockDim.x + threadIdx.x;
    if (idx >= (long)K * N) return;
    int k = (int)(idx / N), n = (int)(idx % N);
    float v = W[idx];
    store_split(h_scratch + outOff, h_scratch + outOff + (long)K * N,
                (long)n * K + k, v);
}

// LayerNorm over rows of 768, output bf16 hi/lo
__global__ void ln_bf16(const float* __restrict__ xext, int useScratch,
                        const float* __restrict__ g, const float* __restrict__ b,
                        long outOff, long loDelta) {
    const float* src = (useScratch ? (const float*)(f_scratch + FO_A) : xext)
                       + (long)blockIdx.x * DD;
    int tid = threadIdx.x;
    float s = 0.f, s2 = 0.f;
    for (int i = tid; i < DD; i += 256) { float v = src[i]; s += v; s2 += v * v; }
    #pragma unroll
    for (int off = 16; off; off >>= 1) {
        s  += __shfl_down_sync(0xffffffffu, s,  off);
        s2 += __shfl_down_sync(0xffffffffu, s2, off);
    }
    __shared__ float sh[2][8];
    int wid = tid >> 5, lane = tid & 31;
    if (lane == 0) { sh[0][wid] = s; sh[1][wid] = s2; }
    __syncthreads();
    if (tid == 0) {
        float ts = 0.f, ts2 = 0.f;
        #pragma unroll
        for (int i = 0; i < 8; i++) { ts += sh[0][i]; ts2 += sh[1][i]; }
        float mean = ts * (1.0f / DD);
        float var = ts2 * (1.0f / DD) - mean * mean;
        sh[0][0] = mean;
        sh[1][0] = rsqrtf(var + 1e-5f);
    }
    __syncthreads();
    float mean = sh[0][0], rstd = sh[1][0];
    long base = outOff + (long)blockIdx.x * DD;
    for (int i = tid; i < DD; i += 256) {
        float v = (src[i] - mean) * rstd * g[i] + b[i];
        store_split(h_scratch, h_scratch + loDelta, base + i, v);
    }
}

// softmax over rows of SS=2048 from f_scratch scores -> probs bf16 hi/lo (1/8 folded)
__global__ void softmax_bf16() {
    long rbase = (long)blockIdx.x * SS;
    const float* p = f_scratch + FO_SCORES + rbase;
    int tid = threadIdx.x;
    float vr[8];
    float mx = -1e30f;
    #pragma unroll
    for (int k = 0; k < 8; k++) {
        float v = p[k * 256 + tid] * 0.125f;
        vr[k] = v;
        mx = fmaxf(mx, v);
    }
    #pragma unroll
    for (int off = 16; off; off >>= 1)
        mx = fmaxf(mx, __shfl_down_sync(0xffffffffu, mx, off));
    __shared__ float sh[8];
    int wid = tid >> 5, lane = tid & 31;
    if (lane == 0) sh[wid] = mx;
    __syncthreads();
    if (tid == 0) {
        float m = sh[0];
        #pragma unroll
        for (int i = 1; i < 8; i++) m = fmaxf(m, sh[i]);
        sh[0] = m;
    }
    __syncthreads();
    mx = sh[0];
    __syncthreads();
    float s = 0.f;
    #pragma unroll
    for (int k = 0; k < 8; k++) { vr[k] = expf(vr[k] - mx); s += vr[k]; }
    #pragma unroll
    for (int off = 16; off; off >>= 1)
        s += __shfl_down_sync(0xffffffffu, s, off);
    if (lane == 0) sh[wid] = s;
    __syncthreads();
    if (tid == 0) {
        float t = 0.f;
        #pragma unroll
        for (int i = 0; i < 8; i++) t += sh[i];
        sh[0] = 1.0f / t;
    }
    __syncthreads();
    float inv = sh[0];
    #pragma unroll
    for (int k = 0; k < 8; k++)
        store_split(h_scratch + HO_PROBS, h_scratch + HO_PROBS + N_PROBS,
                    rbase + k * 256 + tid, vr[k] * inv);
}

// ---------------- tensor-core GEMM (split-bf16 3-term) ----------------
// A: [M,K] row-major bf16 hi/lo.  B: [N,K] K-major bf16 hi/lo.
// MODE 0: Cf[m*ldc+n] = acc (+bias)
// MODE 1: QKV scatter -> Q,K (row-major) / V (transposed), bf16 hi/lo, +bias
// MODE 2: attn-out concat scatter -> Oc bf16 hi/lo (bz = head)
// MODE 3: gelu(acc+bias) -> f bf16 hi/lo
template<int BM, int BN, int BK, int WM, int WN, int MODE>
__global__ void __launch_bounds__(256)
mma_gemm(const __nv_bfloat16* __restrict__ Ahi_, const __nv_bfloat16* __restrict__ Alo_,
         const __nv_bfloat16* __restrict__ Bhi_, const __nv_bfloat16* __restrict__ Blo_,
         const float* __restrict__ bias,
         float* __restrict__ Cf,
         int M, int N, int K, int lda, int ldb, int ldc,
         long sA, long sB, long sC) {
    constexpr int BKP = BK + 8;                 // padded K stride (conflict-free)
    constexpr int WTM = BM / WM, WTN = BN / WN;
    constexpr int MF = WTM / 16, NF = WTN / 8;
    constexpr int STAGE = (2 * BM + 2 * BN) * BKP;   // elems per stage

    extern __shared__ __nv_bfloat16 smem[];
    const int tid = threadIdx.x, lane = tid & 31, warp = tid >> 5;
    const int wm = warp % WM, wn = warp / WM;
    const int m0 = blockIdx.y * BM, n0 = blockIdx.x * BN;
    const int bz = blockIdx.z;

    const __nv_bfloat16* Ahi = Ahi_ + (long)bz * sA;
    const __nv_bfloat16* Alo = Alo_ + (long)bz * sA;
    const __nv_bfloat16* Bhi = Bhi_ + (long)bz * sB;
    const __nv_bfloat16* Blo = Blo_ + (long)bz * sB;

    uint32_t sbase = (uint32_t)__cvta_generic_to_shared(smem);

    auto load_stage = [&](int s, int k0) {
        uint32_t base = sbase + (uint32_t)(s * STAGE) * 2;
        // A tiles (hi & lo)
        for (int i = tid; i < BM * (BK / 8); i += 256) {
            int row = i / (BK / 8), c = i % (BK / 8);
            uint32_t d = base + (uint32_t)(row * BKP + c * 8) * 2;
            long goff = (long)(m0 + row) * lda + k0 + c * 8;
            cpasync16(d, Ahi + goff);
            cpasync16(d + (uint32_t)(BM * BKP) * 2, Alo + goff);
        }
        // B tiles (hi & lo)
        for (int i = tid; i < BN * (BK / 8); i += 256) {
            int row = i / (BK / 8), c = i % (BK / 8);
            uint32_t d = base + (uint32_t)(2 * BM * BKP + row * BKP + c * 8) * 2;
            long goff = (long)(n0 + row) * ldb + k0 + c * 8;
            cpasync16(d, Bhi + goff);
            cpasync16(d + (uint32_t)(BN * BKP) * 2, Blo + goff);
        }
    };

    float acc[MF][NF][4];
    #pragma unroll
    for (int i = 0; i < MF; i++)
        #pragma unroll
        for (int j = 0; j < NF; j++)
            #pragma unroll
            for (int q = 0; q < 4; q++) acc[i][j][q] = 0.f;

    const int nIter = K / BK;
    load_stage(0, 0);
    cp_commit();

    for (int it = 0; it < nIter; ++it) {
        int s = it & 1;
        if (it + 1 < nIter) {
            load_stage(s ^ 1, (it + 1) * BK);
            cp_commit();
            cp_wait<1>();
        } else {
            cp_wait<0>();
        }
        __syncthreads();

        uint32_t base = sbase + (uint32_t)(s * STAGE) * 2;
        #pragma unroll
        for (int kk = 0; kk < BK; kk += 16) {
            uint32_t ahi[MF][4], alo[MF][4], bhi[NF][2], blo[NF][2];
            #pragma unroll
            for (int mf = 0; mf < MF; mf++) {
                int r = wm * WTM + mf * 16 + (lane & 15);
                uint32_t addr = base + (uint32_t)(r * BKP + kk + (lane >> 4) * 8) * 2;
                ldm_x4(ahi[mf], addr);
                ldm_x4(alo[mf], addr + (uint32_t)(BM * BKP) * 2);
            }
            #pragma unroll
            for (int nf2 = 0; nf2 < NF / 2; nf2++) {
                int r = wn * WTN + nf2 * 16 + (lane & 15);
                uint32_t addr = base + (uint32_t)(2 * BM * BKP + r * BKP + kk + (lane >> 4) * 8) * 2;
                uint32_t t[4];
                ldm_x4(t, addr);
                bhi[2 * nf2][0] = t[0]; bhi[2 * nf2][1] = t[2];
                bhi[2 * nf2 + 1][0] = t[1]; bhi[2 * nf2 + 1][1] = t[3];
                ldm_x4(t, addr + (uint32_t)(BN * BKP) * 2);
                blo[2 * nf2][0] = t[0]; blo[2 * nf2][1] = t[2];
                blo[2 * nf2 + 1][0] = t[1]; blo[2 * nf2 + 1][1] = t[3];
            }
            #pragma unroll
            for (int mf = 0; mf < MF; mf++)
                #pragma unroll
                for (int nf = 0; nf < NF; nf++) {
                    mma16816(acc[mf][nf], ahi[mf], bhi[nf]);
                    mma16816(acc[mf][nf], ahi[mf], blo[nf]);
                    mma16816(acc[mf][nf], alo[mf], bhi[nf]);
                }
        }
        __syncthreads();
    }

    // ---------------- epilogue ----------------
    const int tg = lane >> 2, tp = lane & 3;
    #pragma unroll
    for (int mf = 0; mf < MF; mf++) {
        #pragma unroll
        for (int nf = 0; nf < NF; nf++) {
            int mA = m0 + wm * WTM + mf * 16 + tg;
            int nA = n0 + wn * WTN + nf * 8 + tp * 2;
            float v0 = acc[mf][nf][0], v1 = acc[mf][nf][1];
            float v2 = acc[mf][nf][2], v3 = acc[mf][nf][3];
            if (bias) {
                float b0 = bias[nA], b1 = bias[nA + 1];
                v0 += b0; v1 += b1; v2 += b0; v3 += b1;
            }
            if (MODE == 0) {
                float* C = Cf + (long)bz * sC;
                float2 t0 = make_float2(v0, v1);
                float2 t1 = make_float2(v2, v3);
                *(float2*)&C[(long)mA * ldc + nA] = t0;
                *(float2*)&C[(long)(mA + 8) * ldc + nA] = t1;
            } else if (MODE == 1) {
                // QKV scatter
                #pragma unroll
                for (int q = 0; q < 4; q++) {
                    int m = mA + (q >> 1) * 8;
                    int n = nA + (q & 1);
                    float v = (q == 0) ? v0 : (q == 1) ? v1 : (q == 2) ? v2 : v3;
                    int which = n / DD;
                    int r = n - which * DD;
                    int h = r >> 6, e = r & 63;
                    int b = m >> 11, sI = m & 2047;
                    int bh = b * HH + h;
                    if (which == 2) {
                        long idx = ((long)bh * HDIM + e) * SS + sI;
                        store_split(h_scratch + HO_V, h_scratch + HO_V + N_QKV1, idx, v);
                    } else {
                        long idx = ((long)bh * SS + sI) * HDIM + e;
                        long off = (which == 0) ? HO_Q : HO_K;
                        store_split(h_scratch + off, h_scratch + off + N_QKV1, idx, v);
                    }
                }
            } else if (MODE == 2) {
                int b = bz / HH, h = bz % HH;
                #pragma unroll
                for (int q = 0; q < 4; q++) {
                    int m = mA + (q >> 1) * 8;
                    int n = nA + (q & 1);
                    float v = (q == 0) ? v0 : (q == 1) ? v1 : (q == 2) ? v2 : v3;
                    long idx = ((long)(b * SS + m)) * DD + h * HDIM + n;
                    store_split(h_scratch + HO_OC, h_scratch + HO_OC + N_OC, idx, v);
                }
            } else { // MODE 3: gelu -> f hi/lo
                #pragma unroll
                for (int q = 0; q < 4; q++) {
                    int m = mA + (q >> 1) * 8;
                    int n = nA + (q & 1);
                    float v = (q == 0) ? v0 : (q == 1) ? v1 : (q == 2) ? v2 : v3;
                    v = gelu_exact(v);
                    store_split(h_scratch + HO_F, h_scratch + HO_F + N_F,
                                (long)m * FF + n, v);
                }
            }
        }
    }
}

// ---------------- launch ----------------
extern "C" void kernel_launch(void* const* d_in, const int* in_sizes, int n_in,
                              void* d_out, int out_size) {
    const float* x   = (const float*)d_in[0];
    const float* Wq  = (const float*)d_in[1];
    const float* bq  = (const float*)d_in[2];
    const float* Wk  = (const float*)d_in[3];
    const float* bk  = (const float*)d_in[4];
    const float* Wv  = (const float*)d_in[5];
    const float* bv  = (const float*)d_in[6];
    const float* Wo  = (const float*)d_in[7];
    const float* bo  = (const float*)d_in[8];
    const float* W1  = (const float*)d_in[9];
    const float* b1  = (const float*)d_in[10];
    const float* W2  = (const float*)d_in[11];
    const float* b2  = (const float*)d_in[12];
    const float* g1  = (const float*)d_in[13];
    const float* be1 = (const float*)d_in[14];
    const float* g2  = (const float*)d_in[15];
    const float* be2 = (const float*)d_in[16];
    float* out = (float*)d_out;

    // resolve scratch base pointers (host-side symbol lookup)
    static __nv_bfloat16* hs = nullptr;
    static float* fs = nullptr;
    if (!hs) {
        void* p;
        cudaGetSymbolAddress(&p, h_scratch); hs = (__nv_bfloat16*)p;
        cudaGetSymbolAddress(&p, f_scratch); fs = (float*)p;
    }

    const int SMEM_BIG = 2 * ((2 * 128 + 2 * 128) * 40) * 2; // 81920 B
    const int SMEM_ATT = 2 * ((2 * 128 + 2 * 64) * 40) * 2;  // 61440 B
    static bool attrDone = false;
    if (!attrDone) {
        cudaFuncSetAttribute((const void*)mma_gemm<128,128,32,2,4,0>,
                             cudaFuncAttributeMaxDynamicSharedMemorySize, SMEM_BIG);
        cudaFuncSetAttribute((const void*)mma_gemm<128,128,32,2,4,1>,
                             cudaFuncAttributeMaxDynamicSharedMemorySize, SMEM_BIG);
        cudaFuncSetAttribute((const void*)mma_gemm<128,128,32,2,4,3>,
                             cudaFuncAttributeMaxDynamicSharedMemorySize, SMEM_BIG);
        cudaFuncSetAttribute((const void*)mma_gemm<128,64,32,4,2,2>,
                             cudaFuncAttributeMaxDynamicSharedMemorySize, SMEM_ATT);
        attrDone = true;
    }

    // 1) weight/bias packing + conversion
    pack_wqkv<<<(unsigned)((2304L * 768 + 255) / 256), 256>>>(Wq, Wk, Wv);
    pack_bqkv<<<9, 256>>>(bq, bk, bv);
    transpose_w<<<(unsigned)((768L * 768 + 255) / 256), 256>>>(Wo, 768, 768, HO_WO);
    transpose_w<<<(unsigned)((768L * 3072 + 255) / 256), 256>>>(W1, 768, 3072, HO_W1);
    transpose_w<<<(unsigned)((3072L * 768 + 255) / 256), 256>>>(W2, 3072, 768, HO_W2);

    // 2) LN1 -> h (bf16 hi/lo)
    ln_bf16<<<NTOK, 256>>>(x, 0, g1, be1, HO_H, N_H);

    // 3) QKV GEMM with scatter epilogue
    mma_gemm<128,128,32,2,4,1><<<dim3(18, 64, 1), 256, SMEM_BIG>>>(
        hs + HO_H, hs + HO_H + N_H, hs + HO_WQKV, hs + HO_WQKV + N_WQKV,
        fs + FO_BQKV, nullptr,
        NTOK, 3 * DD, DD, DD, DD, 0, 0, 0, 0);

    // 4) scores = Q K^T (batched over 48 heads) -> fp32
    mma_gemm<128,128,32,2,4,0><<<dim3(16, 16, BH), 256, SMEM_BIG>>>(
        hs + HO_Q, hs + HO_Q + N_QKV1, hs + HO_K, hs + HO_K + N_QKV1,
        nullptr, fs + FO_SCORES,
        SS, SS, HDIM, HDIM, HDIM, SS,
        (long)SS * HDIM, (long)SS * HDIM, (long)SS * SS);

    // 5) softmax -> probs (bf16 hi/lo)
    softmax_bf16<<<BH * SS, 256>>>();

    // 6) O = probs @ V (batched) with concat-scatter epilogue
    mma_gemm<128,64,32,4,2,2><<<dim3(1, 16, BH), 256, SMEM_ATT>>>(
        hs + HO_PROBS, hs + HO_PROBS + N_PROBS, hs + HO_V, hs + HO_V + N_QKV1,
        nullptr, nullptr,
        SS, HDIM, SS, SS, SS, 0,
        (long)SS * SS, (long)HDIM * SS, 0);

    // 7) O-proj -> a (fp32)
    mma_gemm<128,128,32,2,4,0><<<dim3(6, 64, 1), 256, SMEM_BIG>>>(
        hs + HO_OC, hs + HO_OC + N_OC, hs + HO_WO, hs + HO_WO + N_WO,
        bo, fs + FO_A,
        NTOK, DD, DD, DD, DD, DD, 0, 0, 0);

    // 8) LN2 -> h2 (bf16 hi/lo)
    ln_bf16<<<NTOK, 256>>>(nullptr, 1, g2, be2, HO_H2, N_H2);

    // 9) MLP1 + GELU -> f (bf16 hi/lo)
    mma_gemm<128,128,32,2,4,3><<<dim3(24, 64, 1), 256, SMEM_BIG>>>(
        hs + HO_H2, hs + HO_H2 + N_H2, hs + HO_W1, hs + HO_W1 + N_W1,
        b1, nullptr,
        NTOK, FF, DD, DD, DD, 0, 0, 0, 0);

    // 10) MLP2 -> out (fp32)
    mma_gemm<128,128,32,2,4,0><<<dim3(6, 64, 1), 256, SMEM_BIG>>>(
        hs + HO_F, hs + HO_F + N_F, hs + HO_W2, hs + HO_W2 + N_W2,
        b2, out,
        NTOK, DD, FF, FF, FF, DD, 0, 0, 0);
}

// round 4
// speedup vs baseline: 2.9433x; 1.2171x over previous
#include <cuda_runtime.h>
#include <cuda_bf16.h>
#include <math.h>
#include <stdint.h>

// ---------------- problem constants ----------------
#define BB   4
#define SS   2048
#define DD   768
#define HH   12
#define HDIM 64
#define FF   3072
#define NTOK 8192
#define BH   48

#define SCALEQ 0.18033688011112042f   // 0.125 * log2(e)

// ---------------- bf16 scratch (hi at off, lo at off + count) ----------------
#define N_H     6291456L
#define N_WQKV  1769472L
#define N_QKV1  6291456L
#define N_OC    6291456L
#define N_WO    589824L
#define N_H2    6291456L
#define N_W1    2359296L
#define N_F     25165824L
#define N_W2    2359296L

#define HO_H     0L
#define HO_WQKV  (HO_H + 2*N_H)
#define HO_Q     (HO_WQKV + 2*N_WQKV)
#define HO_K     (HO_Q + 2*N_QKV1)
#define HO_V     (HO_K + 2*N_QKV1)
#define HO_OC    (HO_V + 2*N_QKV1)
#define HO_WO    (HO_OC + 2*N_OC)
#define HO_H2    (HO_WO + 2*N_WO)
#define HO_W1    (HO_H2 + 2*N_H2)
#define HO_F     (HO_W1 + 2*N_W1)
#define HO_W2    (HO_F + 2*N_F)
#define H_TOTAL  (HO_W2 + 2*N_W2)

#define FO_A      0L
#define FO_BQKV   6291456L
#define F_TOTAL   (FO_BQKV + 2304L)

__device__ __align__(16) __nv_bfloat16 h_scratch[H_TOTAL];
__device__ __align__(16) float        f_scratch[F_TOTAL];

// ---------------- small helpers ----------------
__device__ __forceinline__ void store_split(__nv_bfloat16* hi, __nv_bfloat16* lo,
                                            long idx, float v) {
    __nv_bfloat16 h = __float2bfloat16(v);
    hi[idx] = h;
    lo[idx] = __float2bfloat16(v - __bfloat162float(h));
}

// pack two floats -> bf16x2 hi reg, bf16x2 lo reg
__device__ __forceinline__ uint32_t pack_split2(float x, float y, uint32_t& lo) {
    __nv_bfloat16 hx = __float2bfloat16(x), hy = __float2bfloat16(y);
    __nv_bfloat16 lx = __float2bfloat16(x - __bfloat162float(hx));
    __nv_bfloat16 ly = __float2bfloat16(y - __bfloat162float(hy));
    lo = ((uint32_t)__bfloat16_as_ushort(ly) << 16) | __bfloat16_as_ushort(lx);
    return ((uint32_t)__bfloat16_as_ushort(hy) << 16) | __bfloat16_as_ushort(hx);
}

__device__ __forceinline__ float gelu_exact(float x) {
    return 0.5f * x * (1.0f + erff(x * 0.70710678118654752f));
}

__device__ __forceinline__ void cpasync16(uint32_t dst, const void* src) {
    asm volatile("cp.async.cg.shared.global [%0], [%1], 16;\n" :: "r"(dst), "l"(src));
}
__device__ __forceinline__ void cp_commit() {
    asm volatile("cp.async.commit_group;\n");
}
template<int N> __device__ __forceinline__ void cp_wait() {
    asm volatile("cp.async.wait_group %0;\n" :: "n"(N));
}
__device__ __forceinline__ void ldm_x4(uint32_t* r, uint32_t addr) {
    asm volatile("ldmatrix.sync.aligned.m8n8.x4.shared.b16 {%0,%1,%2,%3}, [%4];\n"
                 : "=r"(r[0]), "=r"(r[1]), "=r"(r[2]), "=r"(r[3]) : "r"(addr));
}
__device__ __forceinline__ void mma16816(float* d, const uint32_t* a, const uint32_t* b) {
    asm volatile("mma.sync.aligned.m16n8k16.row.col.f32.bf16.bf16.f32 "
                 "{%0,%1,%2,%3},{%4,%5,%6,%7},{%8,%9},{%0,%1,%2,%3};\n"
                 : "+f"(d[0]), "+f"(d[1]), "+f"(d[2]), "+f"(d[3])
                 : "r"(a[0]), "r"(a[1]), "r"(a[2]), "r"(a[3]), "r"(b[0]), "r"(b[1]));
}

// ---------------- packing / conversion kernels ----------------
__global__ void pack_wqkv(const float* __restrict__ Wq, const float* __restrict__ Wk,
                          const float* __restrict__ Wv) {
    long idx = (long)blockIdx.x * blockDim.x + threadIdx.x;
    if (idx >= 2304L * 768) return;
    int n = (int)(idx / 768), k = (int)(idx % 768);
    int which = n / DD;
    int r = n - which * DD;
    int h = r >> 6, e = r & 63;
    const float* W = (which == 0) ? Wq : (which == 1) ? Wk : Wv;
    float v = W[(long)h * (DD * HDIM) + (long)k * HDIM + e];
    store_split(h_scratch + HO_WQKV, h_scratch + HO_WQKV + N_WQKV, idx, v);
}

__global__ void pack_bqkv(const float* __restrict__ bq, const float* __restrict__ bk,
                          const float* __restrict__ bv) {
    int idx = blockIdx.x * blockDim.x + threadIdx.x;
    if (idx >= 3 * DD) return;
    int which = idx / DD, r = idx % DD;
    const float* b = (which == 0) ? bq : (which == 1) ? bk : bv;
    f_scratch[FO_BQKV + idx] = b[r];
}

// tiled transpose: out[n*K + k] = W[k*N + n], split hi/lo
__global__ void transpose_w(const float* __restrict__ W, int K, int N, long outOff) {
    __shared__ float t[32][33];
    int bx = blockIdx.x * 32, by = blockIdx.y * 32;
    int tx = threadIdx.x, ty = threadIdx.y;  // block (32,8)
    #pragma unroll
    for (int j = 0; j < 32; j += 8)
        t[ty + j][tx] = W[(long)(by + ty + j) * N + bx + tx];
    __syncthreads();
    __nv_bfloat16* hi = h_scratch + outOff;
    __nv_bfloat16* lo = hi + (long)K * N;
    #pragma unroll
    for (int j = 0; j < 32; j += 8) {
        float v = t[tx][ty + j];
        long idx = (long)(bx + ty + j) * K + by + tx;
        __nv_bfloat16 h = __float2bfloat16(v);
        hi[idx] = h;
        lo[idx] = __float2bfloat16(v - __bfloat162float(h));
    }
}

// LayerNorm over rows of 768, output bf16 hi/lo
__global__ void ln_bf16(const float* __restrict__ xext, int useScratch,
                        const float* __restrict__ g, const float* __restrict__ b,
                        long outOff, long loDelta) {
    const float* src = (useScratch ? (const float*)(f_scratch + FO_A) : xext)
                       + (long)blockIdx.x * DD;
    int tid = threadIdx.x;
    float s = 0.f, s2 = 0.f;
    for (int i = tid; i < DD; i += 256) { float v = src[i]; s += v; s2 += v * v; }
    #pragma unroll
    for (int off = 16; off; off >>= 1) {
        s  += __shfl_down_sync(0xffffffffu, s,  off);
        s2 += __shfl_down_sync(0xffffffffu, s2, off);
    }
    __shared__ float sh[2][8];
    int wid = tid >> 5, lane = tid & 31;
    if (lane == 0) { sh[0][wid] = s; sh[1][wid] = s2; }
    __syncthreads();
    if (tid == 0) {
        float ts = 0.f, ts2 = 0.f;
        #pragma unroll
        for (int i = 0; i < 8; i++) { ts += sh[0][i]; ts2 += sh[1][i]; }
        float mean = ts * (1.0f / DD);
        float var = ts2 * (1.0f / DD) - mean * mean;
        sh[0][0] = mean;
        sh[1][0] = rsqrtf(var + 1e-5f);
    }
    __syncthreads();
    float mean = sh[0][0], rstd = sh[1][0];
    long base = outOff + (long)blockIdx.x * DD;
    for (int i = tid; i < DD; i += 256) {
        float v = (src[i] - mean) * rstd * g[i] + b[i];
        store_split(h_scratch, h_scratch + loDelta, base + i, v);
    }
}

// ---------------- tensor-core GEMM (split-bf16 3-term) ----------------
// A: [M,K] row-major bf16 hi/lo.  B: [N,K] K-major bf16 hi/lo.
// MODE 0: Cf[m*ldc+n] = acc (+bias)
// MODE 1: QKV scatter -> Q (scaled by SCALEQ),K row-major / V transposed, +bias
// MODE 3: gelu(acc+bias) -> f hi/lo
template<int BM, int BN, int BK, int WM, int WN, int MODE>
__global__ void __launch_bounds__(256)
mma_gemm(const __nv_bfloat16* __restrict__ Ahi_, const __nv_bfloat16* __restrict__ Alo_,
         const __nv_bfloat16* __restrict__ Bhi_, const __nv_bfloat16* __restrict__ Blo_,
         const float* __restrict__ bias,
         float* __restrict__ Cf,
         int M, int N, int K, int lda, int ldb, int ldc,
         long sA, long sB, long sC) {
    constexpr int BKP = BK + 8;
    constexpr int WTM = BM / WM, WTN = BN / WN;
    constexpr int MF = WTM / 16, NF = WTN / 8;
    constexpr int STAGE = (2 * BM + 2 * BN) * BKP;

    extern __shared__ __nv_bfloat16 smem[];
    const int tid = threadIdx.x, lane = tid & 31, warp = tid >> 5;
    const int wm = warp % WM, wn = warp / WM;
    const int m0 = blockIdx.y * BM, n0 = blockIdx.x * BN;
    const int bz = blockIdx.z;

    const __nv_bfloat16* Ahi = Ahi_ + (long)bz * sA;
    const __nv_bfloat16* Alo = Alo_ + (long)bz * sA;
    const __nv_bfloat16* Bhi = Bhi_ + (long)bz * sB;
    const __nv_bfloat16* Blo = Blo_ + (long)bz * sB;

    uint32_t sbase = (uint32_t)__cvta_generic_to_shared(smem);

    auto load_stage = [&](int s, int k0) {
        uint32_t base = sbase + (uint32_t)(s * STAGE) * 2;
        for (int i = tid; i < BM * (BK / 8); i += 256) {
            int row = i / (BK / 8), c = i % (BK / 8);
            uint32_t d = base + (uint32_t)(row * BKP + c * 8) * 2;
            long goff = (long)(m0 + row) * lda + k0 + c * 8;
            cpasync16(d, Ahi + goff);
            cpasync16(d + (uint32_t)(BM * BKP) * 2, Alo + goff);
        }
        for (int i = tid; i < BN * (BK / 8); i += 256) {
            int row = i / (BK / 8), c = i % (BK / 8);
            uint32_t d = base + (uint32_t)(2 * BM * BKP + row * BKP + c * 8) * 2;
            long goff = (long)(n0 + row) * ldb + k0 + c * 8;
            cpasync16(d, Bhi + goff);
            cpasync16(d + (uint32_t)(BN * BKP) * 2, Blo + goff);
        }
    };

    float acc[MF][NF][4];
    #pragma unroll
    for (int i = 0; i < MF; i++)
        #pragma unroll
        for (int j = 0; j < NF; j++)
            #pragma unroll
            for (int q = 0; q < 4; q++) acc[i][j][q] = 0.f;

    const int nIter = K / BK;
    load_stage(0, 0);
    cp_commit();

    for (int it = 0; it < nIter; ++it) {
        int s = it & 1;
        if (it + 1 < nIter) {
            load_stage(s ^ 1, (it + 1) * BK);
            cp_commit();
            cp_wait<1>();
        } else {
            cp_wait<0>();
        }
        __syncthreads();

        uint32_t base = sbase + (uint32_t)(s * STAGE) * 2;
        #pragma unroll
        for (int kk = 0; kk < BK; kk += 16) {
            uint32_t ahi[MF][4], alo[MF][4], bhi[NF][2], blo[NF][2];
            #pragma unroll
            for (int mf = 0; mf < MF; mf++) {
                int r = wm * WTM + mf * 16 + (lane & 15);
                uint32_t addr = base + (uint32_t)(r * BKP + kk + (lane >> 4) * 8) * 2;
                ldm_x4(ahi[mf], addr);
                ldm_x4(alo[mf], addr + (uint32_t)(BM * BKP) * 2);
            }
            #pragma unroll
            for (int nf2 = 0; nf2 < NF / 2; nf2++) {
                int r = wn * WTN + nf2 * 16 + (lane & 15);
                uint32_t addr = base + (uint32_t)(2 * BM * BKP + r * BKP + kk + (lane >> 4) * 8) * 2;
                uint32_t t[4];
                ldm_x4(t, addr);
                bhi[2 * nf2][0] = t[0]; bhi[2 * nf2][1] = t[2];
                bhi[2 * nf2 + 1][0] = t[1]; bhi[2 * nf2 + 1][1] = t[3];
                ldm_x4(t, addr + (uint32_t)(BN * BKP) * 2);
                blo[2 * nf2][0] = t[0]; blo[2 * nf2][1] = t[2];
                blo[2 * nf2 + 1][0] = t[1]; blo[2 * nf2 + 1][1] = t[3];
            }
            #pragma unroll
            for (int mf = 0; mf < MF; mf++)
                #pragma unroll
                for (int nf = 0; nf < NF; nf++) {
                    mma16816(acc[mf][nf], ahi[mf], bhi[nf]);
                    mma16816(acc[mf][nf], ahi[mf], blo[nf]);
                    mma16816(acc[mf][nf], alo[mf], bhi[nf]);
                }
        }
        __syncthreads();
    }

    const int tg = lane >> 2, tp = lane & 3;
    #pragma unroll
    for (int mf = 0; mf < MF; mf++) {
        #pragma unroll
        for (int nf = 0; nf < NF; nf++) {
            int mA = m0 + wm * WTM + mf * 16 + tg;
            int nA = n0 + wn * WTN + nf * 8 + tp * 2;
            float v0 = acc[mf][nf][0], v1 = acc[mf][nf][1];
            float v2 = acc[mf][nf][2], v3 = acc[mf][nf][3];
            if (bias) {
                float b0 = bias[nA], b1 = bias[nA + 1];
                v0 += b0; v1 += b1; v2 += b0; v3 += b1;
            }
            if (MODE == 0) {
                float* C = Cf + (long)bz * sC;
                *(float2*)&C[(long)mA * ldc + nA] = make_float2(v0, v1);
                *(float2*)&C[(long)(mA + 8) * ldc + nA] = make_float2(v2, v3);
            } else if (MODE == 1) {
                #pragma unroll
                for (int q = 0; q < 4; q++) {
                    int m = mA + (q >> 1) * 8;
                    int n = nA + (q & 1);
                    float v = (q == 0) ? v0 : (q == 1) ? v1 : (q == 2) ? v2 : v3;
                    int which = n / DD;
                    int r = n - which * DD;
                    int h = r >> 6, e = r & 63;
                    int b = m >> 11, sI = m & 2047;
                    int bh = b * HH + h;
                    if (which == 2) {
                        long idx = ((long)bh * HDIM + e) * SS + sI;
                        store_split(h_scratch + HO_V, h_scratch + HO_V + N_QKV1, idx, v);
                    } else if (which == 0) {
                        long idx = ((long)bh * SS + sI) * HDIM + e;
                        store_split(h_scratch + HO_Q, h_scratch + HO_Q + N_QKV1, idx,
                                    v * SCALEQ);
                    } else {
                        long idx = ((long)bh * SS + sI) * HDIM + e;
                        store_split(h_scratch + HO_K, h_scratch + HO_K + N_QKV1, idx, v);
                    }
                }
            } else { // MODE 3
                #pragma unroll
                for (int q = 0; q < 4; q++) {
                    int m = mA + (q >> 1) * 8;
                    int n = nA + (q & 1);
                    float v = (q == 0) ? v0 : (q == 1) ? v1 : (q == 2) ? v2 : v3;
                    v = gelu_exact(v);
                    store_split(h_scratch + HO_F, h_scratch + HO_F + N_F,
                                (long)m * FF + n, v);
                }
            }
        }
    }
}

// ---------------- flash attention ----------------
// grid: (16 q-tiles, 48 bh). 256 threads. Each warp owns 16 q-rows x all 128 keys.
// K smem: [128 keys][72] hi/lo. V smem: [64 e][136] hi/lo. 2 stages.
#define KSTR 72
#define VSTR 136
#define KBYTES (128 * KSTR * 2)        // 18432
#define VBYTES (64 * VSTR * 2)         // 17408
#define FA_STAGE (2 * KBYTES + 2 * VBYTES)  // 71680
#define FA_SMEM  (2 * FA_STAGE)             // 143360

__global__ void __launch_bounds__(256, 1)
flash_attn() {
    extern __shared__ char fsm[];
    uint32_t sbase = (uint32_t)__cvta_generic_to_shared(fsm);
    const int tid = threadIdx.x, lane = tid & 31, warp = tid >> 5;
    const int tg = lane >> 2, tp = lane & 3;
    const int m0 = blockIdx.x * 128;
    const int bh = blockIdx.y;

    const __nv_bfloat16* Qhi = h_scratch + HO_Q;
    const __nv_bfloat16* Qlo = Qhi + N_QKV1;
    const __nv_bfloat16* Khi = h_scratch + HO_K;
    const __nv_bfloat16* Klo = Khi + N_QKV1;
    const __nv_bfloat16* Vhi = h_scratch + HO_V;
    const __nv_bfloat16* Vlo = Vhi + N_QKV1;

    // ---- load Q fragments into registers (layout-exact) ----
    uint32_t qhi[4][4], qlo[4][4];
    {
        long r0 = (long)bh * SS + m0 + warp * 16 + tg;   // row tg
        #pragma unroll
        for (int ks = 0; ks < 4; ks++) {
            int c0 = ks * 16 + tp * 2;
            qhi[ks][0] = *(const uint32_t*)&Qhi[r0 * 64 + c0];
            qhi[ks][1] = *(const uint32_t*)&Qhi[(r0 + 8) * 64 + c0];
            qhi[ks][2] = *(const uint32_t*)&Qhi[r0 * 64 + c0 + 8];
            qhi[ks][3] = *(const uint32_t*)&Qhi[(r0 + 8) * 64 + c0 + 8];
            qlo[ks][0] = *(const uint32_t*)&Qlo[r0 * 64 + c0];
            qlo[ks][1] = *(const uint32_t*)&Qlo[(r0 + 8) * 64 + c0];
            qlo[ks][2] = *(const uint32_t*)&Qlo[r0 * 64 + c0 + 8];
            qlo[ks][3] = *(const uint32_t*)&Qlo[(r0 + 8) * 64 + c0 + 8];
        }
    }

    auto load_stage = [&](int s, int kk0) {
        uint32_t base = sbase + (uint32_t)(s * FA_STAGE);
        // K chunk hi/lo: 128 rows x 64 elems
        for (int i = tid; i < 128 * 8; i += 256) {
            int row = i >> 3, c = i & 7;
            uint32_t d = base + (uint32_t)(row * KSTR + c * 8) * 2;
            long g = ((long)bh * SS + kk0 + row) * 64 + c * 8;
            cpasync16(d, Khi + g);
            cpasync16(d + KBYTES, Klo + g);
        }
        // V chunk hi/lo: 64 rows x 128 elems (V^T layout)
        for (int i = tid; i < 64 * 16; i += 256) {
            int row = i >> 4, c = i & 15;
            uint32_t d = base + (uint32_t)(2 * KBYTES) + (uint32_t)(row * VSTR + c * 8) * 2;
            long g = ((long)bh * HDIM + row) * SS + kk0 + c * 8;
            cpasync16(d, Vhi + g);
            cpasync16(d + VBYTES, Vlo + g);
        }
    };

    float Oacc[8][4];
    #pragma unroll
    for (int i = 0; i < 8; i++)
        #pragma unroll
        for (int q = 0; q < 4; q++) Oacc[i][q] = 0.f;
    float mrun[2] = { -1e30f, -1e30f };
    float lrun[2] = { 0.f, 0.f };

    load_stage(0, 0);
    cp_commit();

    for (int it = 0; it < 16; ++it) {
        int s = it & 1;
        if (it + 1 < 16) {
            load_stage(s ^ 1, (it + 1) * 128);
            cp_commit();
            cp_wait<1>();
        } else {
            cp_wait<0>();
        }
        __syncthreads();

        uint32_t base = sbase + (uint32_t)(s * FA_STAGE);

        // ---- S = Q K^T (scaled; 3-term split) ----
        float sc[16][4];
        #pragma unroll
        for (int i = 0; i < 16; i++)
            #pragma unroll
            for (int q = 0; q < 4; q++) sc[i][q] = 0.f;

        #pragma unroll
        for (int ks = 0; ks < 4; ks++) {
            #pragma unroll
            for (int nf2 = 0; nf2 < 8; nf2++) {
                int r = nf2 * 16 + (lane & 15);
                uint32_t addr = base + (uint32_t)(r * KSTR + ks * 16 + (lane >> 4) * 8) * 2;
                uint32_t t[4], bhi0[2], bhi1[2], blo0[2], blo1[2];
                ldm_x4(t, addr);
                bhi0[0] = t[0]; bhi0[1] = t[2];
                bhi1[0] = t[1]; bhi1[1] = t[3];
                ldm_x4(t, addr + KBYTES);
                blo0[0] = t[0]; blo0[1] = t[2];
                blo1[0] = t[1]; blo1[1] = t[3];
                mma16816(sc[2 * nf2],     qhi[ks], bhi0);
                mma16816(sc[2 * nf2],     qlo[ks], bhi0);
                mma16816(sc[2 * nf2],     qhi[ks], blo0);
                mma16816(sc[2 * nf2 + 1], qhi[ks], bhi1);
                mma16816(sc[2 * nf2 + 1], qlo[ks], bhi1);
                mma16816(sc[2 * nf2 + 1], qhi[ks], blo1);
            }
        }

        // ---- online softmax (log2 domain; scale already in Q) ----
        float mx0 = mrun[0], mx1 = mrun[1];
        #pragma unroll
        for (int nf = 0; nf < 16; nf++) {
            mx0 = fmaxf(mx0, fmaxf(sc[nf][0], sc[nf][1]));
            mx1 = fmaxf(mx1, fmaxf(sc[nf][2], sc[nf][3]));
        }
        mx0 = fmaxf(mx0, __shfl_xor_sync(0xffffffffu, mx0, 1));
        mx0 = fmaxf(mx0, __shfl_xor_sync(0xffffffffu, mx0, 2));
        mx1 = fmaxf(mx1, __shfl_xor_sync(0xffffffffu, mx1, 1));
        mx1 = fmaxf(mx1, __shfl_xor_sync(0xffffffffu, mx1, 2));

        float alpha0 = exp2f(mrun[0] - mx0);
        float alpha1 = exp2f(mrun[1] - mx1);
        mrun[0] = mx0; mrun[1] = mx1;

        float sum0 = 0.f, sum1 = 0.f;
        #pragma unroll
        for (int nf = 0; nf < 16; nf++) {
            sc[nf][0] = exp2f(sc[nf][0] - mx0);
            sc[nf][1] = exp2f(sc[nf][1] - mx0);
            sc[nf][2] = exp2f(sc[nf][2] - mx1);
            sc[nf][3] = exp2f(sc[nf][3] - mx1);
            sum0 += sc[nf][0] + sc[nf][1];
            sum1 += sc[nf][2] + sc[nf][3];
        }
        sum0 += __shfl_xor_sync(0xffffffffu, sum0, 1);
        sum0 += __shfl_xor_sync(0xffffffffu, sum0, 2);
        sum1 += __shfl_xor_sync(0xffffffffu, sum1, 1);
        sum1 += __shfl_xor_sync(0xffffffffu, sum1, 2);
        lrun[0] = lrun[0] * alpha0 + sum0;
        lrun[1] = lrun[1] * alpha1 + sum1;

        #pragma unroll
        for (int nf = 0; nf < 8; nf++) {
            Oacc[nf][0] *= alpha0; Oacc[nf][1] *= alpha0;
            Oacc[nf][2] *= alpha1; Oacc[nf][3] *= alpha1;
        }

        // ---- O += P V (3-term split; P from registers) ----
        #pragma unroll
        for (int ks = 0; ks < 8; ks++) {
            int u = 2 * ks, vt = 2 * ks + 1;
            uint32_t ahi[4], alo[4];
            ahi[0] = pack_split2(sc[u][0],  sc[u][1],  alo[0]);
            ahi[1] = pack_split2(sc[u][2],  sc[u][3],  alo[1]);
            ahi[2] = pack_split2(sc[vt][0], sc[vt][1], alo[2]);
            ahi[3] = pack_split2(sc[vt][2], sc[vt][3], alo[3]);
            #pragma unroll
            for (int nf2 = 0; nf2 < 4; nf2++) {
                int r = nf2 * 16 + (lane & 15);
                uint32_t addr = base + (uint32_t)(2 * KBYTES)
                              + (uint32_t)(r * VSTR + ks * 16 + (lane >> 4) * 8) * 2;
                uint32_t t[4], bhi0[2], bhi1[2], blo0[2], blo1[2];
                ldm_x4(t, addr);
                bhi0[0] = t[0]; bhi0[1] = t[2];
                bhi1[0] = t[1]; bhi1[1] = t[3];
                ldm_x4(t, addr + VBYTES);
                blo0[0] = t[0]; blo0[1] = t[2];
                blo1[0] = t[1]; blo1[1] = t[3];
                mma16816(Oacc[2 * nf2],     ahi, bhi0);
                mma16816(Oacc[2 * nf2],     alo, bhi0);
                mma16816(Oacc[2 * nf2],     ahi, blo0);
                mma16816(Oacc[2 * nf2 + 1], ahi, bhi1);
                mma16816(Oacc[2 * nf2 + 1], alo, bhi1);
                mma16816(Oacc[2 * nf2 + 1], ahi, blo1);
            }
        }
        __syncthreads();
    }

    // ---- epilogue: O /= l, write concat layout [B,S,D] hi/lo ----
    float inv0 = 1.0f / lrun[0], inv1 = 1.0f / lrun[1];
    int b = bh / HH, h = bh % HH;
    long tok0 = (long)b * SS + m0 + warp * 16 + tg;
    __nv_bfloat16* Ohi = h_scratch + HO_OC;
    __nv_bfloat16* Olo = Ohi + N_OC;
    #pragma unroll
    for (int nf = 0; nf < 8; nf++) {
        int col = h * HDIM + nf * 8 + tp * 2;
        uint32_t lo;
        uint32_t hi = pack_split2(Oacc[nf][0] * inv0, Oacc[nf][1] * inv0, lo);
        *(uint32_t*)&Ohi[tok0 * DD + col] = hi;
        *(uint32_t*)&Olo[tok0 * DD + col] = lo;
        hi = pack_split2(Oacc[nf][2] * inv1, Oacc[nf][3] * inv1, lo);
        *(uint32_t*)&Ohi[(tok0 + 8) * DD + col] = hi;
        *(uint32_t*)&Olo[(tok0 + 8) * DD + col] = lo;
    }
}

// ---------------- launch ----------------
extern "C" void kernel_launch(void* const* d_in, const int* in_sizes, int n_in,
                              void* d_out, int out_size) {
    const float* x   = (const float*)d_in[0];
    const float* Wq  = (const float*)d_in[1];
    const float* bq  = (const float*)d_in[2];
    const float* Wk  = (const float*)d_in[3];
    const float* bk  = (const float*)d_in[4];
    const float* Wv  = (const float*)d_in[5];
    const float* bv  = (const float*)d_in[6];
    const float* Wo  = (const float*)d_in[7];
    const float* bo  = (const float*)d_in[8];
    const float* W1  = (const float*)d_in[9];
    const float* b1  = (const float*)d_in[10];
    const float* W2  = (const float*)d_in[11];
    const float* b2  = (const float*)d_in[12];
    const float* g1  = (const float*)d_in[13];
    const float* be1 = (const float*)d_in[14];
    const float* g2  = (const float*)d_in[15];
    const float* be2 = (const float*)d_in[16];
    float* out = (float*)d_out;

    static __nv_bfloat16* hs = nullptr;
    static float* fs = nullptr;
    if (!hs) {
        void* p;
        cudaGetSymbolAddress(&p, h_scratch); hs = (__nv_bfloat16*)p;
        cudaGetSymbolAddress(&p, f_scratch); fs = (float*)p;
    }

    const int SMEM_BIG = 2 * ((2 * 128 + 2 * 128) * 40) * 2; // 81920 B
    static bool attrDone = false;
    if (!attrDone) {
        cudaFuncSetAttribute((const void*)mma_gemm<128,128,32,2,4,0>,
                             cudaFuncAttributeMaxDynamicSharedMemorySize, SMEM_BIG);
        cudaFuncSetAttribute((const void*)mma_gemm<128,128,32,2,4,1>,
                             cudaFuncAttributeMaxDynamicSharedMemorySize, SMEM_BIG);
        cudaFuncSetAttribute((const void*)mma_gemm<128,128,32,2,4,3>,
                             cudaFuncAttributeMaxDynamicSharedMemorySize, SMEM_BIG);
        cudaFuncSetAttribute((const void*)flash_attn,
                             cudaFuncAttributeMaxDynamicSharedMemorySize, FA_SMEM);
        attrDone = true;
    }

    // 1) weight/bias packing + conversion
    pack_wqkv<<<(unsigned)((2304L * 768 + 255) / 256), 256>>>(Wq, Wk, Wv);
    pack_bqkv<<<9, 256>>>(bq, bk, bv);
    transpose_w<<<dim3(768 / 32, 768 / 32), dim3(32, 8)>>>(Wo, 768, 768, HO_WO);
    transpose_w<<<dim3(3072 / 32, 768 / 32), dim3(32, 8)>>>(W1, 768, 3072, HO_W1);
    transpose_w<<<dim3(768 / 32, 3072 / 32), dim3(32, 8)>>>(W2, 3072, 768, HO_W2);

    // 2) LN1 -> h (bf16 hi/lo)
    ln_bf16<<<NTOK, 256>>>(x, 0, g1, be1, HO_H, N_H);

    // 3) QKV GEMM with scatter epilogue (Q pre-scaled by 0.125*log2e)
    mma_gemm<128,128,32,2,4,1><<<dim3(18, 64, 1), 256, SMEM_BIG>>>(
        hs + HO_H, hs + HO_H + N_H, hs + HO_WQKV, hs + HO_WQKV + N_WQKV,
        fs + FO_BQKV, nullptr,
        NTOK, 3 * DD, DD, DD, DD, 0, 0, 0, 0);

    // 4) fused flash attention -> Oc (concat layout, bf16 hi/lo)
    flash_attn<<<dim3(16, BH), 256, FA_SMEM>>>();

    // 5) O-proj -> a (fp32)
    mma_gemm<128,128,32,2,4,0><<<dim3(6, 64, 1), 256, SMEM_BIG>>>(
        hs + HO_OC, hs + HO_OC + N_OC, hs + HO_WO, hs + HO_WO + N_WO,
        bo, fs + FO_A,
        NTOK, DD, DD, DD, DD, DD, 0, 0, 0);

    // 6) LN2 -> h2 (bf16 hi/lo)
    ln_bf16<<<NTOK, 256>>>(nullptr, 1, g2, be2, HO_H2, N_H2);

    // 7) MLP1 + GELU -> f (bf16 hi/lo)
    mma_gemm<128,128,32,2,4,3><<<dim3(24, 64, 1), 256, SMEM_BIG>>>(
        hs + HO_H2, hs + HO_H2 + N_H2, hs + HO_W1, hs + HO_W1 + N_W1,
        b1, nullptr,
        NTOK, FF, DD, DD, DD, 0, 0, 0, 0);

    // 8) MLP2 -> out (fp32)
    mma_gemm<128,128,32,2,4,0><<<dim3(6, 64, 1), 256, SMEM_BIG>>>(
        hs + HO_F, hs + HO_F + N_F, hs + HO_W2, hs + HO_W2 + N_W2,
        b2, out,
        NTOK, DD, FF, FF, FF, DD, 0, 0, 0);
}

// round 6
// speedup vs baseline: 6.4496x; 2.1913x over previous
#include <cuda_runtime.h>
#include <cuda_fp16.h>
#include <math.h>
#include <stdint.h>

// ---------------- problem constants ----------------
#define BB   4
#define SS   2048
#define DD   768
#define HH   12
#define HDIM 64
#define FF   3072
#define NTOK 8192
#define BH   48

#define SCALEQ 0.18033688011112042f   // 0.125 * log2(e)

// ---------------- fp16 scratch (single precision copies) ----------------
#define N_H     6291456L
#define N_WQKV  1769472L
#define N_QKV1  6291456L
#define N_OC    6291456L
#define N_WO    589824L
#define N_H2    6291456L
#define N_W1    2359296L
#define N_F     25165824L
#define N_W2    2359296L

#define HO_H     0L
#define HO_WQKV  (HO_H    + N_H)
#define HO_Q     (HO_WQKV + N_WQKV)
#define HO_K     (HO_Q    + N_QKV1)
#define HO_V     (HO_K    + N_QKV1)
#define HO_OC    (HO_V    + N_QKV1)
#define HO_WO    (HO_OC   + N_OC)
#define HO_H2    (HO_WO   + N_WO)
#define HO_W1    (HO_H2   + N_H2)
#define HO_F     (HO_W1   + N_W1)
#define HO_W2    (HO_F    + N_F)
#define H_TOTAL  (HO_W2   + N_W2)

#define FO_A      0L
#define FO_BQKV   6291456L
#define F_TOTAL   (FO_BQKV + 2304L)

__device__ __align__(16) __half h_scratch[H_TOTAL];
__device__ __align__(16) float  f_scratch[F_TOTAL];

// ---------------- small helpers ----------------
__device__ __forceinline__ uint32_t pack2h(float x, float y) {
    __half2 h = __floats2half2_rn(x, y);
    return *(uint32_t*)&h;
}

__device__ __forceinline__ float gelu_exact(float x) {
    return 0.5f * x * (1.0f + erff(x * 0.70710678118654752f));
}

__device__ __forceinline__ void cpasync16(uint32_t dst, const void* src) {
    asm volatile("cp.async.cg.shared.global [%0], [%1], 16;\n" :: "r"(dst), "l"(src));
}
__device__ __forceinline__ void cp_commit() {
    asm volatile("cp.async.commit_group;\n");
}
template<int N> __device__ __forceinline__ void cp_wait() {
    asm volatile("cp.async.wait_group %0;\n" :: "n"(N));
}
__device__ __forceinline__ void ldm_x4(uint32_t* r, uint32_t addr) {
    asm volatile("ldmatrix.sync.aligned.m8n8.x4.shared.b16 {%0,%1,%2,%3}, [%4];\n"
                 : "=r"(r[0]), "=r"(r[1]), "=r"(r[2]), "=r"(r[3]) : "r"(addr));
}
__device__ __forceinline__ void mma16816(float* d, const uint32_t* a, const uint32_t* b) {
    asm volatile("mma.sync.aligned.m16n8k16.row.col.f32.f16.f16.f32 "
                 "{%0,%1,%2,%3},{%4,%5,%6,%7},{%8,%9},{%0,%1,%2,%3};\n"
                 : "+f"(d[0]), "+f"(d[1]), "+f"(d[2]), "+f"(d[3])
                 : "r"(a[0]), "r"(a[1]), "r"(a[2]), "r"(a[3]), "r"(b[0]), "r"(b[1]));
}

// ---------------- packing / conversion kernels ----------------
__global__ void pack_wqkv(const float* __restrict__ Wq, const float* __restrict__ Wk,
                          const float* __restrict__ Wv) {
    long idx = (long)blockIdx.x * blockDim.x + threadIdx.x;
    if (idx >= 2304L * 768) return;
    int n = (int)(idx / 768), k = (int)(idx % 768);
    int which = n / DD;
    int r = n - which * DD;
    int h = r >> 6, e = r & 63;
    const float* W = (which == 0) ? Wq : (which == 1) ? Wk : Wv;
    h_scratch[HO_WQKV + idx] = __float2half(W[(long)h * (DD * HDIM) + (long)k * HDIM + e]);
}

__global__ void pack_bqkv(const float* __restrict__ bq, const float* __restrict__ bk,
                          const float* __restrict__ bv) {
    int idx = blockIdx.x * blockDim.x + threadIdx.x;
    if (idx >= 3 * DD) return;
    int which = idx / DD, r = idx % DD;
    const float* b = (which == 0) ? bq : (which == 1) ? bk : bv;
    f_scratch[FO_BQKV + idx] = b[r];
}

// tiled transpose: out[n*K + k] = W[k*N + n]
__global__ void transpose_w(const float* __restrict__ W, int K, int N, long outOff) {
    __shared__ float t[32][33];
    int bx = blockIdx.x * 32, by = blockIdx.y * 32;
    int tx = threadIdx.x, ty = threadIdx.y;  // block (32,8)
    #pragma unroll
    for (int j = 0; j < 32; j += 8)
        t[ty + j][tx] = W[(long)(by + ty + j) * N + bx + tx];
    __syncthreads();
    __half* o = h_scratch + outOff;
    #pragma unroll
    for (int j = 0; j < 32; j += 8)
        o[(long)(bx + ty + j) * K + by + tx] = __float2half(t[tx][ty + j]);
}

// LayerNorm over rows of 768, output fp16
__global__ void ln_fp16(const float* __restrict__ xext, int useScratch,
                        const float* __restrict__ g, const float* __restrict__ b,
                        long outOff) {
    const float* src = (useScratch ? (const float*)(f_scratch + FO_A) : xext)
                       + (long)blockIdx.x * DD;
    int tid = threadIdx.x;
    float s = 0.f, s2 = 0.f;
    for (int i = tid; i < DD; i += 256) { float v = src[i]; s += v; s2 += v * v; }
    #pragma unroll
    for (int off = 16; off; off >>= 1) {
        s  += __shfl_down_sync(0xffffffffu, s,  off);
        s2 += __shfl_down_sync(0xffffffffu, s2, off);
    }
    __shared__ float sh[2][8];
    int wid = tid >> 5, lane = tid & 31;
    if (lane == 0) { sh[0][wid] = s; sh[1][wid] = s2; }
    __syncthreads();
    if (tid == 0) {
        float ts = 0.f, ts2 = 0.f;
        #pragma unroll
        for (int i = 0; i < 8; i++) { ts += sh[0][i]; ts2 += sh[1][i]; }
        float mean = ts * (1.0f / DD);
        float var = ts2 * (1.0f / DD) - mean * mean;
        sh[0][0] = mean;
        sh[1][0] = rsqrtf(var + 1e-5f);
    }
    __syncthreads();
    float mean = sh[0][0], rstd = sh[1][0];
    long base = outOff + (long)blockIdx.x * DD;
    for (int i = tid; i < DD; i += 256) {
        float v = (src[i] - mean) * rstd * g[i] + b[i];
        h_scratch[base + i] = __float2half(v);
    }
}

// ---------------- fp16 tensor-core GEMM (single term) ----------------
// A: [M,K] K-major fp16.  B: [N,K] K-major fp16.
// MODE 0: Cf[m*ldc+n] = acc + bias (fp32)
// MODE 1: QKV scatter -> Q (scaled), K row-major / V transposed, +bias, fp16
// MODE 3: gelu(acc+bias) -> f fp16
template<int BM, int BN, int BK, int WM, int WN, int MODE>
__global__ void __launch_bounds__(256)
mma_gemm(const __half* __restrict__ A, const __half* __restrict__ B,
         const float* __restrict__ bias, float* __restrict__ Cf,
         int M, int N, int K, int lda, int ldb, int ldc) {
    constexpr int BKP = BK + 8;
    constexpr int WTM = BM / WM, WTN = BN / WN;
    constexpr int MF = WTM / 16, NF = WTN / 8;
    constexpr int STAGE = (BM + BN) * BKP;     // halfs per stage

    extern __shared__ __half smem[];
    const int tid = threadIdx.x, lane = tid & 31, warp = tid >> 5;
    const int wm = warp % WM, wn = warp / WM;
    const int m0 = blockIdx.y * BM, n0 = blockIdx.x * BN;

    uint32_t sbase = (uint32_t)__cvta_generic_to_shared(smem);

    auto load_stage = [&](int s, int k0) {
        uint32_t base = sbase + (uint32_t)(s * STAGE) * 2;
        #pragma unroll 2
        for (int i = tid; i < BM * (BK / 8); i += 256) {
            int row = i / (BK / 8), c = i % (BK / 8);
            cpasync16(base + (uint32_t)(row * BKP + c * 8) * 2,
                      A + (long)(m0 + row) * lda + k0 + c * 8);
        }
        #pragma unroll 2
        for (int i = tid; i < BN * (BK / 8); i += 256) {
            int row = i / (BK / 8), c = i % (BK / 8);
            cpasync16(base + (uint32_t)(BM * BKP + row * BKP + c * 8) * 2,
                      B + (long)(n0 + row) * ldb + k0 + c * 8);
        }
    };

    float acc[MF][NF][4];
    #pragma unroll
    for (int i = 0; i < MF; i++)
        #pragma unroll
        for (int j = 0; j < NF; j++)
            #pragma unroll
            for (int q = 0; q < 4; q++) acc[i][j][q] = 0.f;

    const int nIter = K / BK;
    load_stage(0, 0);
    cp_commit();

    for (int it = 0; it < nIter; ++it) {
        int s = it & 1;
        if (it + 1 < nIter) {
            load_stage(s ^ 1, (it + 1) * BK);
            cp_commit();
            cp_wait<1>();
        } else {
            cp_wait<0>();
        }
        __syncthreads();

        uint32_t base = sbase + (uint32_t)(s * STAGE) * 2;
        #pragma unroll
        for (int kk = 0; kk < BK; kk += 16) {
            uint32_t af[MF][4], bf[NF][2];
            #pragma unroll
            for (int mf = 0; mf < MF; mf++) {
                int r = wm * WTM + mf * 16 + (lane & 15);
                ldm_x4(af[mf], base + (uint32_t)(r * BKP + kk + (lane >> 4) * 8) * 2);
            }
            #pragma unroll
            for (int nf2 = 0; nf2 < NF / 2; nf2++) {
                int r = wn * WTN + nf2 * 16 + (lane & 15);
                uint32_t t[4];
                ldm_x4(t, base + (uint32_t)(BM * BKP + r * BKP + kk + (lane >> 4) * 8) * 2);
                bf[2 * nf2][0] = t[0]; bf[2 * nf2][1] = t[2];
                bf[2 * nf2 + 1][0] = t[1]; bf[2 * nf2 + 1][1] = t[3];
            }
            #pragma unroll
            for (int mf = 0; mf < MF; mf++)
                #pragma unroll
                for (int nf = 0; nf < NF; nf++)
                    mma16816(acc[mf][nf], af[mf], bf[nf]);
        }
        __syncthreads();
    }

    const int tg = lane >> 2, tp = lane & 3;
    #pragma unroll
    for (int mf = 0; mf < MF; mf++) {
        #pragma unroll
        for (int nf = 0; nf < NF; nf++) {
            int mA = m0 + wm * WTM + mf * 16 + tg;
            int nA = n0 + wn * WTN + nf * 8 + tp * 2;
            float v0 = acc[mf][nf][0], v1 = acc[mf][nf][1];
            float v2 = acc[mf][nf][2], v3 = acc[mf][nf][3];
            if (bias) {
                float b0 = bias[nA], b1 = bias[nA + 1];
                v0 += b0; v1 += b1; v2 += b0; v3 += b1;
            }
            if (MODE == 0) {
                *(float2*)&Cf[(long)mA * ldc + nA] = make_float2(v0, v1);
                *(float2*)&Cf[(long)(mA + 8) * ldc + nA] = make_float2(v2, v3);
            } else if (MODE == 1) {
                #pragma unroll
                for (int q = 0; q < 4; q++) {
                    int m = mA + (q >> 1) * 8;
                    int n = nA + (q & 1);
                    float v = (q == 0) ? v0 : (q == 1) ? v1 : (q == 2) ? v2 : v3;
                    int which = n / DD;
                    int r = n - which * DD;
                    int h = r >> 6, e = r & 63;
                    int bI = m >> 11, sI = m & 2047;
                    int bh = bI * HH + h;
                    if (which == 2) {
                        h_scratch[HO_V + ((long)bh * HDIM + e) * SS + sI] = __float2half(v);
                    } else if (which == 0) {
                        h_scratch[HO_Q + ((long)bh * SS + sI) * HDIM + e] =
                            __float2half(v * SCALEQ);
                    } else {
                        h_scratch[HO_K + ((long)bh * SS + sI) * HDIM + e] = __float2half(v);
                    }
                }
            } else { // MODE 3: gelu -> f
                #pragma unroll
                for (int q = 0; q < 4; q++) {
                    int m = mA + (q >> 1) * 8;
                    int n = nA + (q & 1);
                    float v = (q == 0) ? v0 : (q == 1) ? v1 : (q == 2) ? v2 : v3;
                    h_scratch[HO_F + (long)m * FF + n] = __float2half(gelu_exact(v));
                }
            }
        }
    }
}

// ---------------- flash attention (single fp16) ----------------
// grid: (16 q-tiles, 48 bh). 256 threads. Warp = 16 q-rows x all 128 keys.
#define KSTR 72
#define VSTR 136
#define KBYTES (128 * KSTR * 2)           // 18432
#define VBYTES (64 * VSTR * 2)            // 17408
#define FA_STAGE (KBYTES + VBYTES)        // 35840
#define FA_SMEM  (2 * FA_STAGE)           // 71680

__global__ void __launch_bounds__(256, 1)
flash_attn() {
    extern __shared__ char fsm[];
    uint32_t sbase = (uint32_t)__cvta_generic_to_shared(fsm);
    const int tid = threadIdx.x, lane = tid & 31, warp = tid >> 5;
    const int tg = lane >> 2, tp = lane & 3;
    const int m0 = blockIdx.x * 128;
    const int bh = blockIdx.y;

    const __half* Q = h_scratch + HO_Q;
    const __half* Kp = h_scratch + HO_K;
    const __half* Vp = h_scratch + HO_V;

    // Q fragments (layout-exact register loads)
    uint32_t qf[4][4];
    {
        long r0 = (long)bh * SS + m0 + warp * 16 + tg;
        #pragma unroll
        for (int ks = 0; ks < 4; ks++) {
            int c0 = ks * 16 + tp * 2;
            qf[ks][0] = *(const uint32_t*)&Q[r0 * 64 + c0];
            qf[ks][1] = *(const uint32_t*)&Q[(r0 + 8) * 64 + c0];
            qf[ks][2] = *(const uint32_t*)&Q[r0 * 64 + c0 + 8];
            qf[ks][3] = *(const uint32_t*)&Q[(r0 + 8) * 64 + c0 + 8];
        }
    }

    auto load_stage = [&](int s, int kk0) {
        uint32_t base = sbase + (uint32_t)(s * FA_STAGE);
        for (int i = tid; i < 128 * 8; i += 256) {
            int row = i >> 3, c = i & 7;
            cpasync16(base + (uint32_t)(row * KSTR + c * 8) * 2,
                      Kp + ((long)bh * SS + kk0 + row) * 64 + c * 8);
        }
        for (int i = tid; i < 64 * 16; i += 256) {
            int row = i >> 4, c = i & 15;
            cpasync16(base + (uint32_t)KBYTES + (uint32_t)(row * VSTR + c * 8) * 2,
                      Vp + ((long)bh * HDIM + row) * SS + kk0 + c * 8);
        }
    };

    float Oacc[8][4];
    #pragma unroll
    for (int i = 0; i < 8; i++)
        #pragma unroll
        for (int q = 0; q < 4; q++) Oacc[i][q] = 0.f;
    float mrun[2] = { -1e30f, -1e30f };
    float lrun[2] = { 0.f, 0.f };

    load_stage(0, 0);
    cp_commit();

    for (int it = 0; it < 16; ++it) {
        int s = it & 1;
        if (it + 1 < 16) {
            load_stage(s ^ 1, (it + 1) * 128);
            cp_commit();
            cp_wait<1>();
        } else {
            cp_wait<0>();
        }
        __syncthreads();

        uint32_t base = sbase + (uint32_t)(s * FA_STAGE);

        // ---- S = Q K^T (scale folded in Q) ----
        float sc[16][4];
        #pragma unroll
        for (int i = 0; i < 16; i++)
            #pragma unroll
            for (int q = 0; q < 4; q++) sc[i][q] = 0.f;

        #pragma unroll
        for (int ks = 0; ks < 4; ks++) {
            #pragma unroll
            for (int nf2 = 0; nf2 < 8; nf2++) {
                int r = nf2 * 16 + (lane & 15);
                uint32_t t[4], b0[2], b1[2];
                ldm_x4(t, base + (uint32_t)(r * KSTR + ks * 16 + (lane >> 4) * 8) * 2);
                b0[0] = t[0]; b0[1] = t[2];
                b1[0] = t[1]; b1[1] = t[3];
                mma16816(sc[2 * nf2],     qf[ks], b0);
                mma16816(sc[2 * nf2 + 1], qf[ks], b1);
            }
        }

        // ---- online softmax (exp2 domain) ----
        float mx0 = mrun[0], mx1 = mrun[1];
        #pragma unroll
        for (int nf = 0; nf < 16; nf++) {
            mx0 = fmaxf(mx0, fmaxf(sc[nf][0], sc[nf][1]));
            mx1 = fmaxf(mx1, fmaxf(sc[nf][2], sc[nf][3]));
        }
        mx0 = fmaxf(mx0, __shfl_xor_sync(0xffffffffu, mx0, 1));
        mx0 = fmaxf(mx0, __shfl_xor_sync(0xffffffffu, mx0, 2));
        mx1 = fmaxf(mx1, __shfl_xor_sync(0xffffffffu, mx1, 1));
        mx1 = fmaxf(mx1, __shfl_xor_sync(0xffffffffu, mx1, 2));

        float alpha0 = exp2f(mrun[0] - mx0);
        float alpha1 = exp2f(mrun[1] - mx1);
        mrun[0] = mx0; mrun[1] = mx1;

        float sum0 = 0.f, sum1 = 0.f;
        #pragma unroll
        for (int nf = 0; nf < 16; nf++) {
            sc[nf][0] = exp2f(sc[nf][0] - mx0);
            sc[nf][1] = exp2f(sc[nf][1] - mx0);
            sc[nf][2] = exp2f(sc[nf][2] - mx1);
            sc[nf][3] = exp2f(sc[nf][3] - mx1);
            sum0 += sc[nf][0] + sc[nf][1];
            sum1 += sc[nf][2] + sc[nf][3];
        }
        sum0 += __shfl_xor_sync(0xffffffffu, sum0, 1);
        sum0 += __shfl_xor_sync(0xffffffffu, sum0, 2);
        sum1 += __shfl_xor_sync(0xffffffffu, sum1, 1);
        sum1 += __shfl_xor_sync(0xffffffffu, sum1, 2);
        lrun[0] = lrun[0] * alpha0 + sum0;
        lrun[1] = lrun[1] * alpha1 + sum1;

        #pragma unroll
        for (int nf = 0; nf < 8; nf++) {
            Oacc[nf][0] *= alpha0; Oacc[nf][1] *= alpha0;
            Oacc[nf][2] *= alpha1; Oacc[nf][3] *= alpha1;
        }

        // ---- O += P V (P packed fp16 from registers) ----
        #pragma unroll
        for (int ks = 0; ks < 8; ks++) {
            int u = 2 * ks, vt = 2 * ks + 1;
            uint32_t af[4];
            af[0] = pack2h(sc[u][0],  sc[u][1]);
            af[1] = pack2h(sc[u][2],  sc[u][3]);
            af[2] = pack2h(sc[vt][0], sc[vt][1]);
            af[3] = pack2h(sc[vt][2], sc[vt][3]);
            #pragma unroll
            for (int nf2 = 0; nf2 < 4; nf2++) {
                int r = nf2 * 16 + (lane & 15);
                uint32_t t[4], b0[2], b1[2];
                ldm_x4(t, base + (uint32_t)KBYTES
                           + (uint32_t)(r * VSTR + ks * 16 + (lane >> 4) * 8) * 2);
                b0[0] = t[0]; b0[1] = t[2];
                b1[0] = t[1]; b1[1] = t[3];
                mma16816(Oacc[2 * nf2],     af, b0);
                mma16816(Oacc[2 * nf2 + 1], af, b1);
            }
        }
        __syncthreads();
    }

    // ---- epilogue: O /= l, write concat layout [B,S,D] fp16 ----
    float inv0 = 1.0f / lrun[0], inv1 = 1.0f / lrun[1];
    int b = bh / HH, h = bh % HH;
    long tok0 = (long)b * SS + m0 + warp * 16 + tg;
    __half* O = h_scratch + HO_OC;
    #pragma unroll
    for (int nf = 0; nf < 8; nf++) {
        int col = h * HDIM + nf * 8 + tp * 2;
        *(uint32_t*)&O[tok0 * DD + col] =
            pack2h(Oacc[nf][0] * inv0, Oacc[nf][1] * inv0);
        *(uint32_t*)&O[(tok0 + 8) * DD + col] =
            pack2h(Oacc[nf][2] * inv1, Oacc[nf][3] * inv1);
    }
}

// ---------------- launch ----------------
extern "C" void kernel_launch(void* const* d_in, const int* in_sizes, int n_in,
                              void* d_out, int out_size) {
    const float* x   = (const float*)d_in[0];
    const float* Wq  = (const float*)d_in[1];
    const float* bq  = (const float*)d_in[2];
    const float* Wk  = (const float*)d_in[3];
    const float* bk  = (const float*)d_in[4];
    const float* Wv  = (const float*)d_in[5];
    const float* bv  = (const float*)d_in[6];
    const float* Wo  = (const float*)d_in[7];
    const float* bo  = (const float*)d_in[8];
    const float* W1  = (const float*)d_in[9];
    const float* b1  = (const float*)d_in[10];
    const float* W2  = (const float*)d_in[11];
    const float* b2  = (const float*)d_in[12];
    const float* g1  = (const float*)d_in[13];
    const float* be1 = (const float*)d_in[14];
    const float* g2  = (const float*)d_in[15];
    const float* be2 = (const float*)d_in[16];
    float* out = (float*)d_out;

    static __half* hs = nullptr;
    static float* fs = nullptr;
    if (!hs) {
        void* p;
        cudaGetSymbolAddress(&p, h_scratch); hs = (__half*)p;
        cudaGetSymbolAddress(&p, f_scratch); fs = (float*)p;
    }

    const int SMEM_GEMM = 2 * ((128 + 128) * 40) * 2;   // 40960 B
    static bool attrDone = false;
    if (!attrDone) {
        cudaFuncSetAttribute((const void*)mma_gemm<128,128,32,2,4,0>,
                             cudaFuncAttributeMaxDynamicSharedMemorySize, SMEM_GEMM);
        cudaFuncSetAttribute((const void*)mma_gemm<128,128,32,2,4,1>,
                             cudaFuncAttributeMaxDynamicSharedMemorySize, SMEM_GEMM);
        cudaFuncSetAttribute((const void*)mma_gemm<128,128,32,2,4,3>,
                             cudaFuncAttributeMaxDynamicSharedMemorySize, SMEM_GEMM);
        cudaFuncSetAttribute((const void*)flash_attn,
                             cudaFuncAttributeMaxDynamicSharedMemorySize, FA_SMEM);
        attrDone = true;
    }

    // 1) weight/bias packing + conversion
    pack_wqkv<<<(unsigned)((2304L * 768 + 255) / 256), 256>>>(Wq, Wk, Wv);
    pack_bqkv<<<9, 256>>>(bq, bk, bv);
    transpose_w<<<dim3(768 / 32, 768 / 32), dim3(32, 8)>>>(Wo, 768, 768, HO_WO);
    transpose_w<<<dim3(3072 / 32, 768 / 32), dim3(32, 8)>>>(W1, 768, 3072, HO_W1);
    transpose_w<<<dim3(768 / 32, 3072 / 32), dim3(32, 8)>>>(W2, 3072, 768, HO_W2);

    // 2) LN1 -> h (fp16)
    ln_fp16<<<NTOK, 256>>>(x, 0, g1, be1, HO_H);

    // 3) QKV GEMM with scatter epilogue (Q pre-scaled by 0.125*log2e)
    mma_gemm<128,128,32,2,4,1><<<dim3(18, 64), 256, SMEM_GEMM>>>(
        hs + HO_H, hs + HO_WQKV, fs + FO_BQKV, nullptr,
        NTOK, 3 * DD, DD, DD, DD, 0);

    // 4) fused flash attention -> Oc (concat layout, fp16)
    flash_attn<<<dim3(16, BH), 256, FA_SMEM>>>();

    // 5) O-proj -> a (fp32)
    mma_gemm<128,128,32,2,4,0><<<dim3(6, 64), 256, SMEM_GEMM>>>(
        hs + HO_OC, hs + HO_WO, bo, fs + FO_A,
        NTOK, DD, DD, DD, DD, DD);

    // 6) LN2 -> h2 (fp16)
    ln_fp16<<<NTOK, 256>>>(nullptr, 1, g2, be2, HO_H2);

    // 7) MLP1 + GELU -> f (fp16)
    mma_gemm<128,128,32,2,4,3><<<dim3(24, 64), 256, SMEM_GEMM>>>(
        hs + HO_H2, hs + HO_W1, b1, nullptr,
        NTOK, FF, DD, DD, DD, 0);

    // 8) MLP2 -> out (fp32)
    mma_gemm<128,128,32,2,4,0><<<dim3(6, 64), 256, SMEM_GEMM>>>(
        hs + HO_F, hs + HO_W2, b2, out,
        NTOK, DD, FF, FF, FF, DD);
}